// round 5
// baseline (speedup 1.0000x reference)
#include <cuda_runtime.h>

#define NN 8192
#define DD 128
#define PP 256
#define KK 256
#define DEG 32
#define FF 16
#define INV_TEMP (1.0f / 0.07f)
#define FULL 0xffffffffu

// Scratch (__device__ globals; no allocations allowed)
__device__ float g_t1[PP], g_t2[PP], g_posc[PP], g_neg[KK];
__device__ int   g_count = 0;

__device__ __forceinline__ float warp_sum(float v) {
#pragma unroll
    for (int o = 16; o; o >>= 1) v += __shfl_xor_sync(FULL, v, o);
    return v;
}

__device__ __forceinline__ float dot4(float4 a, float4 b) {
    return a.x * b.x + a.y * b.y + a.z * b.z + a.w * b.w;
}

// ---------------------------------------------------------------------------
// Grid = 2*PP = 512 blocks x 512 threads (16 warps).
//   block b in [0,PP):   term1 for neighbor i=b, plus mu_xy/pos/core
//   block b in [PP,2PP): term2 for neighbor i=b-PP, plus negative i
// Warp w handles rows 2w, 2w+1 of the 32-row neighborhood (5 warp reductions).
// Align loss (term1+term2) computed by the last-arriving block.
// ---------------------------------------------------------------------------
__global__ void __launch_bounds__(512)
fused_kernel(const float* __restrict__ z,
             const float* __restrict__ et,
             const float* __restrict__ ct,
             const float* __restrict__ core,
             const float* __restrict__ omega,
             const float* __restrict__ phi,
             const int* __restrict__ qidx,
             const int* __restrict__ neg_idxs,
             const int* __restrict__ nbr_idxs,
             const int* __restrict__ neighbors,
             float* __restrict__ out) {
    __shared__ float s_mu[DEG], s_te[DEG];
    __shared__ float s_ws[8];
    __shared__ bool  s_isLast;

    const int t = threadIdx.x, lane = t & 31, warp = t >> 5;
    const int b = blockIdx.x;
    const bool isT1 = (b < PP);
    const int  i = isT1 ? b : b - PP;

    // ---- level-0 scalars ----
    const int   q   = qidx[0];
    const int   nbr = nbr_idxs[i];
    const float ct0 = ct[0];
    const int   baseRow = isT1 ? q : nbr;   // whose neighborhood
    const int   refRow  = isT1 ? nbr : q;   // vector dotted against rows

    float cq = 0.f, ci = 0.f;
    if (isT1 && t == 0) { cq = core[q]; ci = core[nbr]; }

    // ---- level-1: warp's two neighbor indices (broadcast LDG.64, no shfl) ----
    const int2 ii = ((const int2*)(neighbors + baseRow * DEG))[warp];
    const float4 ref4 = ((const float4*)(z + (long long)refRow * DD))[lane];

    // extras: term1 warp0 -> z_q for mu_xy ; term2 warp15 -> negative row
    float4 aux4 = make_float4(0.f, 0.f, 0.f, 0.f);
    if (isT1) {
        if (warp == 0) aux4 = ((const float4*)(z + (long long)q * DD))[lane];
    } else if (warp == 15) {
        const int negy = neg_idxs[i];
        aux4 = ((const float4*)(z + (long long)negy * DD))[lane];
    }

    // ---- level-2: the two rows + per-lane edge-time (half-warp split) ----
    const int myRow = (lane < 16) ? ii.x : ii.y;
    const float4 row0 = ((const float4*)(z + (long long)ii.x * DD))[lane];
    const float4 row1 = ((const float4*)(z + (long long)ii.y * DD))[lane];
    const float mydt = ct0 - et[(long long)baseRow * NN + myRow];

    // ---- reference-vector norm ----
    const float nref = warp_sum(dot4(ref4, ref4));
    const float rref = rsqrtf(fmaxf(nref, 1e-24f));
    const float aref = nref * rref * rref;   // ||ref_hat||^2

    // ---- time encodings: 16 lanes per dt, 1 sinf each + 4 butterflies ----
    {
        const int sub = lane & 15;
        float p = (sub < FF - 1) ? __sinf(omega[1 + sub] * mydt + phi[1 + sub])
                                 : (omega[0] * mydt + phi[0]);
        p += __shfl_xor_sync(FULL, p, 1);
        p += __shfl_xor_sync(FULL, p, 2);
        p += __shfl_xor_sync(FULL, p, 4);
        p += __shfl_xor_sync(FULL, p, 8);
        if (lane == 0)  s_te[2 * warp]     = p;
        if (lane == 16) s_te[2 * warp + 1] = p;
    }

    // ---- row dots -> mu values (2 rows per warp) ----
    {
        const float n0 = warp_sum(dot4(row0, row0));
        const float d0 = warp_sum(dot4(ref4, row0));
        const float n1 = warp_sum(dot4(row1, row1));
        const float d1 = warp_sum(dot4(ref4, row1));
        if (lane == 0) {
            const float r0 = rsqrtf(fmaxf(n0, 1e-24f));
            s_mu[2 * warp]     = -(aref + n0 * r0 * r0 - 2.f * rref * r0 * d0);
            const float r1 = rsqrtf(fmaxf(n1, 1e-24f));
            s_mu[2 * warp + 1] = -(aref + n1 * r1 * r1 - 2.f * rref * r1 * d1);
        }
    }

    // ---- per-block extras ----
    float mu_xy = 0.f;
    if (isT1) {
        if (warp == 0) {
            const float nq_ = warp_sum(dot4(aux4, aux4));
            const float dqi = warp_sum(dot4(aux4, ref4));
            const float rq  = rsqrtf(fmaxf(nq_, 1e-24f));
            const float aq  = nq_ * rq * rq;
            mu_xy = -(aq + aref - 2.f * rq * rref * dqi);   // lane0 uses it
        }
    } else if (warp == 15) {
        const float nn = warp_sum(dot4(aux4, aux4));
        const float dn = warp_sum(dot4(aux4, ref4));        // ref4 here is z_q
        if (lane == 0) {
            const float rn = rsqrtf(fmaxf(nn, 1e-24f));
            const float an = nn * rn * rn;
            const float mu = -(aref + an - 2.f * rref * rn * dn);
            const float sg = 1.f / (1.f + __expf(-mu));
            g_neg[i] = -__logf(1.f - sg + 1e-8f) * (1.f / KK);
        }
    }
    __syncthreads();  // publish s_mu / s_te

    // ---- softmax (warp 0), exact reference formula ----
    if (warp == 0) {
        const float mu = s_mu[lane];
        const float w = __expf(mu * INV_TEMP - s_te[lane]);
        const float S = warp_sum(w);
        const float a = w / (S + 1e-8f);
        const float term = warp_sum(a * mu);
        if (lane == 0) {
            if (isT1) {
                g_t1[i] = term;
                const float sg = 1.f / (1.f + __expf(-mu_xy));
                const float dc = ci - cq;
                g_posc[i] = -__logf(sg + 1e-8f) * (1.f / PP)
                          + (0.1f / PP) * dc * dc;
            } else {
                g_t2[i] = term;
            }
        }
    }

    // ---- completion: last-arriving block computes align + total ----
    __threadfence();
    __syncthreads();
    if (t == 0) {
        const int c = atomicAdd(&g_count, 1);
        s_isLast = (c == (int)gridDim.x - 1);
    }
    __syncthreads();
    if (s_isLast) {
        __threadfence();
        float s = 0.f;
        if (t < PP) {
            const float dd = g_t1[t] + g_t2[t];      // lambda_T - lambda_S
            const float ad = fabsf(dd);
            const float al = (ad < 1.f) ? 0.5f * dd * dd : (ad - 0.5f);
            s = g_posc[t] + g_neg[t] + al * (0.1f / PP);
        }
        s = warp_sum(s);
        if (lane == 0 && warp < 8) s_ws[warp] = s;
        __syncthreads();
        if (t == 0) {
            float tot = 0.f;
#pragma unroll
            for (int w = 0; w < 8; w++) tot += s_ws[w];
            out[0] = tot;
            g_count = 0;  // reset for next graph replay
        }
    }
}

// ---------------------------------------------------------------------------
// Inputs (metadata order):
// 0 z [N*D] f32, 1 edge_times [N*N] f32, 2 current_time [1] f32,
// 3 core_values [N] f32, 4 omega [F] f32, 5 phi [F] f32,
// 6 query_idx [1] i32, 7 neg_idxs [K] i32, 8 neighbor_idxs [P] i32,
// 9 neighbors [N*DEG] i32. Output: [1] f32.
// ---------------------------------------------------------------------------
extern "C" void kernel_launch(void* const* d_in, const int* in_sizes, int n_in,
                              void* d_out, int out_size) {
    const float* z     = (const float*)d_in[0];
    const float* et    = (const float*)d_in[1];
    const float* ct    = (const float*)d_in[2];
    const float* core  = (const float*)d_in[3];
    const float* omega = (const float*)d_in[4];
    const float* phi   = (const float*)d_in[5];
    const int*   qidx  = (const int*)d_in[6];
    const int*   negi  = (const int*)d_in[7];
    const int*   nbri  = (const int*)d_in[8];
    const int*   nbrs  = (const int*)d_in[9];

    fused_kernel<<<2 * PP, 512>>>(z, et, ct, core, omega, phi,
                                  qidx, negi, nbri, nbrs, (float*)d_out);
}

// round 6
// speedup vs baseline: 1.4060x; 1.4060x over previous
#include <cuda_runtime.h>

#define NN 8192
#define DD 128
#define PP 256
#define KK 256
#define DEG 32
#define FF 16
#define INV_TEMP (1.0f / 0.07f)
#define FULL 0xffffffffu

// Scratch (__device__ globals; no allocations allowed)
__device__ float g_t1[PP], g_t2[PP], g_posc[PP], g_neg[KK];
__device__ int   g_count = 0;

__device__ __forceinline__ float warp_sum(float v) {
#pragma unroll
    for (int o = 16; o; o >>= 1) v += __shfl_xor_sync(FULL, v, o);
    return v;
}

__device__ __forceinline__ float dot4(float4 a, float4 b) {
    return a.x * b.x + a.y * b.y + a.z * b.z + a.w * b.w;
}

// ---------------------------------------------------------------------------
// Grid = 2*PP = 512 blocks x 512 threads (16 warps).
//   block b in [0,PP):   term1 for neighbor i=b, plus mu_xy/pos/core
//   block b in [PP,2PP): term2 for neighbor i=b-PP, plus negative i
// Warp w owns rows 2w,2w+1; 16-lane group g = lane>>4 owns one row.
// One 4-level butterfly reduces {row norm, ref·row, ref norm, time enc}
// simultaneously -> minimal shfl count, no redundant block work.
// Align loss (term1+term2) computed by the last-arriving block.
// ---------------------------------------------------------------------------
__global__ void __launch_bounds__(512)
fused_kernel(const float* __restrict__ z,
             const float* __restrict__ et,
             const float* __restrict__ ct,
             const float* __restrict__ core,
             const float* __restrict__ omega,
             const float* __restrict__ phi,
             const int* __restrict__ qidx,
             const int* __restrict__ neg_idxs,
             const int* __restrict__ nbr_idxs,
             const int* __restrict__ neighbors,
             float* __restrict__ out) {
    __shared__ float s_mu[DEG], s_te[DEG];
    __shared__ float s_ws[8];
    __shared__ bool  s_isLast;

    const int t = threadIdx.x, lane = t & 31, warp = t >> 5;
    const int s = lane & 15;             // position within 16-lane group
    const int b = blockIdx.x;
    const bool isT1 = (b < PP);
    const int  i = isT1 ? b : b - PP;

    // ---- level-0 scalars (broadcast loads) ----
    const int   q   = qidx[0];
    const int   nbr = nbr_idxs[i];
    const float ct0 = ct[0];
    const int   baseRow = isT1 ? q : nbr;   // whose neighborhood
    const int   refRow  = isT1 ? nbr : q;   // vector dotted against rows

    float cq = 0.f, ci = 0.f;
    if (isT1 && t == 0) { cq = core[q]; ci = core[nbr]; }

    // ---- level-1: this warp's two neighbor indices (broadcast LDG.64) ----
    const int2 ii = ((const int2*)(neighbors + baseRow * DEG))[warp];
    const int myRow = (lane < 16) ? ii.x : ii.y;

    const float4* refp = (const float4*)(z + (long long)refRow * DD);
    const float4* rowp = (const float4*)(z + (long long)myRow * DD);

    // ---- level-2: row + ref segments (16 dims per lane) + edge time ----
    const float4 r0 = rowp[s],      r1 = rowp[s + 16];
    const float4 f0 = refp[s],      f1 = refp[s + 16];
    float dt0 = 0.f;
    if (s == 0) dt0 = ct0 - et[(long long)baseRow * NN + myRow];
    const float dtv = __shfl_sync(FULL, dt0, lane & 16);

    // extras: term1 warp0 -> z_q for mu_xy ; term2 warp15 -> negative row
    float4 aux4 = make_float4(0.f, 0.f, 0.f, 0.f);
    float4 reff = make_float4(0.f, 0.f, 0.f, 0.f);
    if (isT1) {
        if (warp == 0) {
            aux4 = ((const float4*)(z + (long long)q * DD))[lane];
            reff = refp[lane];
        }
    } else if (warp == 15) {
        const int negy = neg_idxs[i];
        aux4 = ((const float4*)(z + (long long)negy * DD))[lane];
        reff = refp[lane];
    }

    // ---- per-lane partials ----
    float nr = dot4(r0, r0) + dot4(r1, r1);   // row norm partial
    float dr = dot4(f0, r0) + dot4(f1, r1);   // ref . row partial
    float nf = dot4(f0, f0) + dot4(f1, f1);   // ref norm partial
    float te = (s < FF - 1) ? __sinf(omega[1 + s] * dtv + phi[1 + s])
                            : (omega[0] * dtv + phi[0]);

    // ---- one 4-level butterfly reduces all four within the 16-lane group ----
#pragma unroll
    for (int o = 8; o; o >>= 1) {
        nr += __shfl_xor_sync(FULL, nr, o);
        dr += __shfl_xor_sync(FULL, dr, o);
        nf += __shfl_xor_sync(FULL, nf, o);
        te += __shfl_xor_sync(FULL, te, o);
    }
    float aref = 0.f, rref = 0.f;
    if (s == 0) {
        rref = rsqrtf(fmaxf(nf, 1e-24f));
        aref = nf * rref * rref;                       // ||ref_hat||^2
        const float rr = rsqrtf(fmaxf(nr, 1e-24f));
        const int j = 2 * warp + (lane >> 4);
        s_mu[j] = -(aref + nr * rr * rr - 2.f * rref * rr * dr);
        s_te[j] = te;
    }

    // ---- per-block extras (full-warp reductions, one warp each) ----
    float mu_xy = 0.f;
    if (isT1) {
        if (warp == 0) {
            const float nq_ = warp_sum(dot4(aux4, aux4));
            const float dqi = warp_sum(dot4(aux4, reff));
            // aref/rref live in lane 0 (s==0 of group 0)
            const float arefb = __shfl_sync(FULL, aref, 0);
            const float rrefb = __shfl_sync(FULL, rref, 0);
            const float rq = rsqrtf(fmaxf(nq_, 1e-24f));
            const float aq = nq_ * rq * rq;
            mu_xy = -(aq + arefb - 2.f * rq * rrefb * dqi);
        }
    } else if (warp == 15) {
        const float nn = warp_sum(dot4(aux4, aux4));
        const float dn = warp_sum(dot4(aux4, reff));
        const float arefb = __shfl_sync(FULL, aref, 0);
        const float rrefb = __shfl_sync(FULL, rref, 0);
        if (lane == 0) {
            const float rn = rsqrtf(fmaxf(nn, 1e-24f));
            const float an = nn * rn * rn;
            const float mu = -(arefb + an - 2.f * rrefb * rn * dn);
            const float sg = 1.f / (1.f + __expf(-mu));
            g_neg[i] = -__logf(1.f - sg + 1e-8f) * (1.f / KK);
        }
    }
    __syncthreads();  // publish s_mu / s_te

    // ---- softmax (warp 0), exact reference formula ----
    if (warp == 0) {
        const float mu = s_mu[lane];
        const float w = __expf(mu * INV_TEMP - s_te[lane]);
        const float S = warp_sum(w);
        const float a = w / (S + 1e-8f);
        const float term = warp_sum(a * mu);
        if (lane == 0) {
            if (isT1) {
                g_t1[i] = term;
                const float sg = 1.f / (1.f + __expf(-mu_xy));
                const float dc = ci - cq;
                g_posc[i] = -__logf(sg + 1e-8f) * (1.f / PP)
                          + (0.1f / PP) * dc * dc;
            } else {
                g_t2[i] = term;
            }
        }
    }

    // ---- completion: last-arriving block computes align + total ----
    __threadfence();
    __syncthreads();
    if (t == 0) {
        const int c = atomicAdd(&g_count, 1);
        s_isLast = (c == (int)gridDim.x - 1);
    }
    __syncthreads();
    if (s_isLast) {
        __threadfence();
        float sv = 0.f;
        if (t < PP) {
            const float dd = g_t1[t] + g_t2[t];      // lambda_T - lambda_S
            const float ad = fabsf(dd);
            const float al = (ad < 1.f) ? 0.5f * dd * dd : (ad - 0.5f);
            sv = g_posc[t] + g_neg[t] + al * (0.1f / PP);
        }
        sv = warp_sum(sv);
        if (lane == 0 && warp < 8) s_ws[warp] = sv;
        __syncthreads();
        if (t == 0) {
            float tot = 0.f;
#pragma unroll
            for (int w = 0; w < 8; w++) tot += s_ws[w];
            out[0] = tot;
            g_count = 0;  // reset for next graph replay
        }
    }
}

// ---------------------------------------------------------------------------
// Inputs (metadata order):
// 0 z [N*D] f32, 1 edge_times [N*N] f32, 2 current_time [1] f32,
// 3 core_values [N] f32, 4 omega [F] f32, 5 phi [F] f32,
// 6 query_idx [1] i32, 7 neg_idxs [K] i32, 8 neighbor_idxs [P] i32,
// 9 neighbors [N*DEG] i32. Output: [1] f32.
// ---------------------------------------------------------------------------
extern "C" void kernel_launch(void* const* d_in, const int* in_sizes, int n_in,
                              void* d_out, int out_size) {
    const float* z     = (const float*)d_in[0];
    const float* et    = (const float*)d_in[1];
    const float* ct    = (const float*)d_in[2];
    const float* core  = (const float*)d_in[3];
    const float* omega = (const float*)d_in[4];
    const float* phi   = (const float*)d_in[5];
    const int*   qidx  = (const int*)d_in[6];
    const int*   negi  = (const int*)d_in[7];
    const int*   nbri  = (const int*)d_in[8];
    const int*   nbrs  = (const int*)d_in[9];

    fused_kernel<<<2 * PP, 512>>>(z, et, ct, core, omega, phi,
                                  qidx, negi, nbri, nbrs, (float*)d_out);
}